// round 5
// baseline (speedup 1.0000x reference)
#include <cuda_runtime.h>
#include <math.h>

#define Nx   256
#define BN   2048      // 8*256

// ---------------- scratch ----------------
__device__ float g_A [BN*128];   // h @ Wm1[0:128]
__device__ float g_Bm[BN*128];   // h @ Wm1[128:256]
__device__ float g_P [BN*128];   // h @ Wu_top
__device__ float g_as[BN];
__device__ float g_bs[BN];
__device__ float g_S [BN*128];   // sum_j w_ij * relu(pre_ij)
__device__ float g_c [BN];       // sum_j w_ij
__device__ float g_M [128*128];  // Wm2 @ Wu_bot
__device__ float g_vb[128];      // bm2 @ Wu_bot + bu

typedef unsigned long long u64;

__device__ __forceinline__ u64 dup2(float a) {
    u64 r; unsigned au = __float_as_uint(a);
    asm("mov.b64 %0, {%1, %1};" : "=l"(r) : "r"(au));
    return r;
}
__device__ __forceinline__ u64 add2v(u64 a, u64 b) {
    u64 r; asm("add.rn.f32x2 %0, %1, %2;" : "=l"(r) : "l"(a), "l"(b));
    return r;
}
__device__ __forceinline__ u64 fma2v(u64 a, u64 b, u64 c) {
    u64 r; asm("fma.rn.f32x2 %0, %1, %2, %3;" : "=l"(r) : "l"(a), "l"(b), "l"(c));
    return r;
}
__device__ __forceinline__ void fma2a(u64& acc, u64 a, u64 b) {
    asm("fma.rn.f32x2 %0, %1, %2, %0;" : "+l"(acc) : "l"(a), "l"(b));
}
__device__ __forceinline__ float2 unpk(u64 v) {
    unsigned lo, hi;
    asm("mov.b64 {%0, %1}, %2;" : "=r"(lo), "=r"(hi) : "l"(v));
    return make_float2(__uint_as_float(lo), __uint_as_float(hi));
}
__device__ __forceinline__ u64 pack2(float x, float y) {
    u64 r;
    asm("mov.b64 %0, {%1, %2};" : "=l"(r)
        : "r"(__float_as_uint(x)), "r"(__float_as_uint(y)));
    return r;
}
__device__ __forceinline__ u64 relu2(u64 v) {
    float2 f = unpk(v);
    return pack2(fmaxf(f.x, 0.f), fmaxf(f.y, 0.f));
}

// =======================================================================
// Stage 1: grid 145 = one wave.
//  bid 0..127  : h rows [16*bid, +16) x W-panel [Wm1t|Wm1b|Wut] (384 cols)
//  bid 128..135: Wm2 rows x Wu_bot -> g_M
//  bid 136..143: attention dots (256 rows each)
//  bid 144     : vb
// block 512, dyn smem 204800
// =======================================================================
#define S1_SMEM ((128*384 + 16*128) * 4)

__global__ void __launch_bounds__(512) k_stage1(
    const float* __restrict__ h,   const float* __restrict__ Wm1,
    const float* __restrict__ Wa,  const float* __restrict__ Wm2,
    const float* __restrict__ bm2, const float* __restrict__ Wu,
    const float* __restrict__ bu)
{
    extern __shared__ float sm[];
    float* Ws = sm;                 // [128][384] (or [128][128] for M blocks)
    float* As = sm + 128*384;       // [16][128]
    const int bid = blockIdx.x;
    const int t   = threadIdx.x;
    const int ty = t >> 5, lane = t & 31;

    if (bid < 128) {
        // ---- fill W panel: 3 x (128x128)
        const float* Wp0 = Wm1;
        const float* Wp1 = Wm1 + 128*128;
        const float* Wp2 = Wu;
#pragma unroll
        for (int n = 0; n < 8; n++) {
            int idx = t + n*512;           // 0..4095 float4 per panel
            int wk = idx >> 5, wn = (idx & 31) * 4;
            *(float4*)&Ws[wk*384 + wn]       = *(const float4*)&Wp0[wk*128 + wn];
            *(float4*)&Ws[wk*384 + 128 + wn] = *(const float4*)&Wp1[wk*128 + wn];
            *(float4*)&Ws[wk*384 + 256 + wn] = *(const float4*)&Wp2[wk*128 + wn];
        }
        // ---- fill A tile 16x128
        *(float4*)&As[t*4] = *(const float4*)&h[bid*16*128 + t*4];
        __syncthreads();

        u64 acc[6];
#pragma unroll
        for (int i = 0; i < 6; i++) acc[i] = 0ull;

#pragma unroll 2
        for (int k0 = 0; k0 < 128; k0 += 4) {
            float4 a4 = *(const float4*)&As[ty*128 + k0];   // warp broadcast
#pragma unroll
            for (int kk = 0; kk < 4; kk++) {
                float av = (kk==0) ? a4.x : (kk==1) ? a4.y : (kk==2) ? a4.z : a4.w;
                u64 aa = dup2(av);
                const float* wrow = &Ws[(k0 + kk)*384 + lane*4];
                ulonglong2 w0 = *(const ulonglong2*)&wrow[0];
                ulonglong2 w1 = *(const ulonglong2*)&wrow[128];
                ulonglong2 w2 = *(const ulonglong2*)&wrow[256];
                fma2a(acc[0], aa, w0.x); fma2a(acc[1], aa, w0.y);
                fma2a(acc[2], aa, w1.x); fma2a(acc[3], aa, w1.y);
                fma2a(acc[4], aa, w2.x); fma2a(acc[5], aa, w2.y);
            }
        }
        const long row = bid*16 + ty;
        float2 p, q;
        p = unpk(acc[0]); q = unpk(acc[1]);
        *(float4*)&g_A [row*128 + lane*4] = make_float4(p.x, p.y, q.x, q.y);
        p = unpk(acc[2]); q = unpk(acc[3]);
        *(float4*)&g_Bm[row*128 + lane*4] = make_float4(p.x, p.y, q.x, q.y);
        p = unpk(acc[4]); q = unpk(acc[5]);
        *(float4*)&g_P [row*128 + lane*4] = make_float4(p.x, p.y, q.x, q.y);

    } else if (bid < 136) {
        // ---- g_M tile: Wm2 rows (bid-128)*16.. x Wu_bot
        const float* Wp = Wu + 128*128;
#pragma unroll
        for (int n = 0; n < 8; n++) {
            int idx = t + n*512;
            int wk = idx >> 5, wn = (idx & 31) * 4;
            *(float4*)&Ws[wk*128 + wn] = *(const float4*)&Wp[wk*128 + wn];
        }
        *(float4*)&As[t*4] = *(const float4*)&Wm2[(bid-128)*16*128 + t*4];
        __syncthreads();

        u64 acc0 = 0ull, acc1 = 0ull;
#pragma unroll 4
        for (int k0 = 0; k0 < 128; k0 += 4) {
            float4 a4 = *(const float4*)&As[ty*128 + k0];
#pragma unroll
            for (int kk = 0; kk < 4; kk++) {
                float av = (kk==0) ? a4.x : (kk==1) ? a4.y : (kk==2) ? a4.z : a4.w;
                u64 aa = dup2(av);
                ulonglong2 w = *(const ulonglong2*)&Ws[(k0+kk)*128 + lane*4];
                fma2a(acc0, aa, w.x); fma2a(acc1, aa, w.y);
            }
        }
        float2 p = unpk(acc0), q = unpk(acc1);
        *(float4*)&g_M[((bid-128)*16 + ty)*128 + lane*4] =
            make_float4(p.x, p.y, q.x, q.y);

    } else if (bid < 144) {
        // ---- dots: rows (bid-136)*256 .. +256, warp per 16 rows
        const int rowbase = (bid - 136) * 256 + ty * 16;
        float4 wa1 = *(const float4*)&Wa[lane*4];
        float4 wa2 = *(const float4*)&Wa[128 + lane*4];
#pragma unroll 4
        for (int rr = 0; rr < 16; rr++) {
            int row = rowbase + rr;
            float4 hv = *(const float4*)&h[row*128 + lane*4];
            float sa = hv.x*wa1.x + hv.y*wa1.y + hv.z*wa1.z + hv.w*wa1.w;
            float sb = hv.x*wa2.x + hv.y*wa2.y + hv.z*wa2.z + hv.w*wa2.w;
#pragma unroll
            for (int o = 16; o; o >>= 1) {
                sa += __shfl_xor_sync(0xffffffffu, sa, o);
                sb += __shfl_xor_sync(0xffffffffu, sb, o);
            }
            if (lane == 0) { g_as[row] = sa; g_bs[row] = sb; }
        }
    } else {
        if (t < 128) {
            float acc = bu[t];
#pragma unroll 16
            for (int k = 0; k < 128; k++)
                acc = fmaf(bm2[k], Wu[(128 + k)*128 + t], acc);
            g_vb[t] = acc;
        }
    }
}

// =======================================================================
// k_pair: softmax + weighted relu aggregation -> g_S, g_c
// grid (16,8), block 512, dyn smem 205824
// =======================================================================
#define PAIR_SMEM ((32768 + 16384 + 2048 + 256) * 4)

__global__ void __launch_bounds__(512, 1) k_pair(
    const float* __restrict__ dist, const int* __restrict__ adj,
    const float* __restrict__ Wm1,  const float* __restrict__ bm1,
    const float* __restrict__ Wa,   const float* __restrict__ ba)
{
    extern __shared__ float sm[];
    float*  Bsh  = sm;                       // 256*128
    float4* dwsh = (float4*)(sm + 32768);    // [16][256] {d,d,w,w}
    float*  Ash  = sm + 32768 + 16384;       // 16*128 (A + bm1)
    float*  bssh = Ash + 2048;               // 256

    const int t = threadIdx.x;
    const int b = blockIdx.y, i0 = blockIdx.x * 16;
    const int lane = t & 31, wrp = t >> 5;

    // ---- fills
    {
        const float4* src = (const float4*)(g_Bm + (long)b*Nx*128);
        float4* d4 = (float4*)Bsh;
#pragma unroll
        for (int k = 0; k < 16; k++) d4[t + k*512] = src[t + k*512];
    }
#pragma unroll
    for (int k = 0; k < 4; k++) {
        int idx = t + k*512;
        Ash[idx] = g_A[(long)(b*Nx + i0)*128 + idx] + bm1[idx & 127];
    }
    if (t < 256) bssh[t] = g_bs[b*Nx + t];
    __syncthreads();

    // ---- phase 1: warp wrp -> i = i0 + wrp
    const float wa_d = Wa[256];
    {
        const int ig = b*Nx + i0 + wrp;
        const float a_i = g_as[ig] + ba[0];
        float l[8], dv[8]; int mk[8];
#pragma unroll
        for (int jj = 0; jj < 8; jj++) {
            int j = jj*32 + lane;
            float d = dist[(long)ig*Nx + j];
            int   m = adj [(long)ig*Nx + j];
            float x = fmaf(d, wa_d, a_i + bssh[j]);
            x = (x >= 0.f) ? x : 0.2f * x;
            l[jj] = m ? x : -1e9f;
            dv[jj] = d; mk[jj] = m;
        }
        float mx = l[0];
#pragma unroll
        for (int jj = 1; jj < 8; jj++) mx = fmaxf(mx, l[jj]);
#pragma unroll
        for (int o = 16; o; o >>= 1) mx = fmaxf(mx, __shfl_xor_sync(0xffffffffu, mx, o));
        float sum = 0.f, cs = 0.f;
#pragma unroll
        for (int jj = 0; jj < 8; jj++) {
            float e = expf(l[jj] - mx);
            l[jj] = e; sum += e;
            cs += mk[jj] ? e : 0.f;
        }
#pragma unroll
        for (int o = 16; o; o >>= 1) {
            sum += __shfl_xor_sync(0xffffffffu, sum, o);
            cs  += __shfl_xor_sync(0xffffffffu, cs,  o);
        }
        float inv = 1.f / sum;
#pragma unroll
        for (int jj = 0; jj < 8; jj++) {
            int j = jj*32 + lane;
            float w = mk[jj] ? l[jj]*inv : 0.f;
            dwsh[wrp*256 + j] = make_float4(dv[jj], dv[jj], w, w);
        }
        if (lane == 0) g_c[ig] = cs * inv;
    }

    // ---- phase 2 registers
    const int cp = t & 63, q = t >> 6;
    u64 a2[16], acc2[16];
#pragma unroll
    for (int i = 0; i < 16; i++) {
        a2[i]   = *(const u64*)&Ash[i*128 + cp*2];
        acc2[i] = 0ull;
    }
    const u64 wd2 = *(const u64*)&Wm1[256*128 + cp*2];
    __syncthreads();

    // ---- phase 2: schedulable (no compound volatile asm)
    const ulonglong2* dwp = (const ulonglong2*)dwsh;
#pragma unroll 1
    for (int jj = 0; jj < 32; jj++) {
        int j = jj*8 + q;
        u64 b2 = *(const u64*)&Bsh[j*128 + cp*2];
#pragma unroll
        for (int i = 0; i < 16; i++) {
            ulonglong2 dw = dwp[i*256 + j];      // warp-broadcast LDS.128
            u64 x = fma2v(dw.x, wd2, add2v(a2[i], b2));
            acc2[i] = fma2v(dw.y, relu2(x), acc2[i]);
        }
    }
    __syncthreads();   // done reading Bsh & dwsh

    // ---- reduce over q via smem overlay on dwsh
    u64* part = (u64*)dwsh;   // [16][8][64]
#pragma unroll
    for (int i = 0; i < 16; i++) part[(i*8 + q)*64 + cp] = acc2[i];
    __syncthreads();
#pragma unroll
    for (int rep = 0; rep < 2; rep++) {
        int it = t + rep*512;
        int i = it >> 6, cpp = it & 63;
        float2 s = make_float2(0.f, 0.f);
#pragma unroll
        for (int qq = 0; qq < 8; qq++) {
            float2 v = unpk(part[(i*8 + qq)*64 + cpp]);
            s.x += v.x; s.y += v.y;
        }
        *(float2*)&g_S[(long)(b*Nx + i0 + i)*128 + cpp*2] = s;
    }
}

// =======================================================================
// k_out: out = relu( g_P + S@M + g_c*vb )
// grid 128, block 512, 16 rows/block, dyn smem (128*132 + 16*128)*4
// =======================================================================
#define KO_SMEM ((128*132 + 16*128) * 4)

__global__ void __launch_bounds__(512) k_out(float* __restrict__ out)
{
    extern __shared__ float sm[];
    float* Ms = sm;              // [128][132]
    float* Ss = sm + 128*132;    // [16][128]
    const int t = threadIdx.x;
    const int ty = t >> 5, lane = t & 31;
    const int row0 = blockIdx.x * 16;

#pragma unroll
    for (int n = 0; n < 8; n++) {
        int idx = t + n*512;
        int wk = idx >> 5, wn = (idx & 31) * 4;
        *(float4*)&Ms[wk*132 + wn] = *(const float4*)&g_M[wk*128 + wn];
    }
    *(float4*)&Ss[t*4] = *(const float4*)&g_S[(long)row0*128 + t*4];
    __syncthreads();

    u64 acc0 = 0ull, acc1 = 0ull;
#pragma unroll 4
    for (int k0 = 0; k0 < 128; k0 += 4) {
        float4 a4 = *(const float4*)&Ss[ty*128 + k0];   // broadcast
#pragma unroll
        for (int kk = 0; kk < 4; kk++) {
            float av = (kk==0) ? a4.x : (kk==1) ? a4.y : (kk==2) ? a4.z : a4.w;
            u64 aa = dup2(av);
            ulonglong2 w = *(const ulonglong2*)&Ms[(k0+kk)*132 + lane*4];
            fma2a(acc0, aa, w.x); fma2a(acc1, aa, w.y);
        }
    }

    const int row = row0 + ty;
    float cr = g_c[row];
    float4 vb4 = *(const float4*)&g_vb[lane*4];
    float4 pv  = *(const float4*)&g_P[(long)row*128 + lane*4];
    float2 p = unpk(acc0), q = unpk(acc1);
    float4 o;
    o.x = fmaxf(pv.x + fmaf(cr, vb4.x, p.x), 0.f);
    o.y = fmaxf(pv.y + fmaf(cr, vb4.y, p.y), 0.f);
    o.z = fmaxf(pv.z + fmaf(cr, vb4.z, q.x), 0.f);
    o.w = fmaxf(pv.w + fmaf(cr, vb4.w, q.y), 0.f);
    *(float4*)&out[(long)row*128 + lane*4] = o;
}

// =======================================================================
extern "C" void kernel_launch(void* const* d_in, const int* in_sizes, int n_in,
                              void* d_out, int out_size)
{
    const float* h    = (const float*)d_in[0];
    const int*   adj  = (const int*)  d_in[1];
    const float* dist = (const float*)d_in[2];
    const float* Wm1  = (const float*)d_in[3];
    const float* bm1  = (const float*)d_in[4];
    const float* Wm2  = (const float*)d_in[5];
    const float* bm2  = (const float*)d_in[6];
    const float* Wa   = (const float*)d_in[7];
    const float* ba   = (const float*)d_in[8];
    const float* Wu   = (const float*)d_in[9];
    const float* bu   = (const float*)d_in[10];
    float* out = (float*)d_out;

    cudaFuncSetAttribute(k_stage1, cudaFuncAttributeMaxDynamicSharedMemorySize,
                         S1_SMEM);
    cudaFuncSetAttribute(k_pair, cudaFuncAttributeMaxDynamicSharedMemorySize,
                         PAIR_SMEM);
    cudaFuncSetAttribute(k_out, cudaFuncAttributeMaxDynamicSharedMemorySize,
                         KO_SMEM);

    k_stage1<<<145, 512, S1_SMEM>>>(h, Wm1, Wa, Wm2, bm2, Wu, bu);
    k_pair  <<<dim3(16, 8), 512, PAIR_SMEM>>>(dist, adj, Wm1, bm1, Wa, ba);
    k_out   <<<128, 512, KO_SMEM>>>(out);
}